// round 1
// baseline (speedup 1.0000x reference)
#include <cuda_runtime.h>
#include <cuda_bf16.h>
#include <cstddef>

// Problem constants
#define NB    2
#define SLEN  2048
#define EMB   1024          // H=16, D=64
#define SCH   64            // number of S-chunks for the column-sum
#define SPER  (SLEN / SCH)  // 32 rows per chunk

// Scratch (no allocations allowed) — ~528 KB total
__device__ float g_part[SCH][NB][EMB];  // partial column sums of `values`
__device__ float g_t[NB][EMB];          // t = blockdiag(Wv) @ sv
__device__ float g_y[NB][EMB];          // y = Wo @ t + bo

// ---------------------------------------------------------------------------
// K1: partial column sums over S.  Grid (SCH, NB) x 256 threads, float4.
// Each block reads SPER contiguous rows (128 KB), fully coalesced.
// ---------------------------------------------------------------------------
__global__ void k_colsum_partial(const float* __restrict__ vals)
{
    const int n = blockIdx.y;
    const int c = blockIdx.x;
    const int t = threadIdx.x;  // 0..255 -> float4 lane over EMB

    const float4* __restrict__ base =
        (const float4*)(vals + (size_t)n * SLEN * EMB + (size_t)c * SPER * EMB);

    float4 acc = make_float4(0.f, 0.f, 0.f, 0.f);
    #pragma unroll 8
    for (int s = 0; s < SPER; ++s) {
        float4 v = base[s * (EMB / 4) + t];
        acc.x += v.x; acc.y += v.y; acc.z += v.z; acc.w += v.w;
    }
    ((float4*)g_part[c][n])[t] = acc;
}

// ---------------------------------------------------------------------------
// K2: finish sv reduction (fixed order -> deterministic) and apply the
// block-diagonal per-head Wv: t[n, h*64+d] = sum_d' Wv[d,d'] * sv[n, h*64+d'].
// Grid (NB) x 1024 threads.
// ---------------------------------------------------------------------------
__global__ void k_wv(const float* __restrict__ Wv)
{
    const int n = blockIdx.x;
    const int e = threadIdx.x;  // 0..1023

    float sv = 0.f;
    #pragma unroll
    for (int c = 0; c < SCH; ++c) sv += g_part[c][n][e];

    __shared__ float s_sv[EMB];
    s_sv[e] = sv;
    __syncthreads();

    const int h = e >> 6;
    const int d = e & 63;
    const float* __restrict__ wrow = Wv + d * 64;     // Wv[d, :]
    const float* __restrict__ svh  = s_sv + h * 64;

    float acc = 0.f;
    #pragma unroll 16
    for (int dp = 0; dp < 64; ++dp) acc += wrow[dp] * svh[dp];

    g_t[n][e] = acc;
}

// ---------------------------------------------------------------------------
// K3: y[n][e] = Wo[e,:] . t[n] + bo[e].  One warp per output element;
// lanes stride the row with float4 (coalesced). 2048 warps = 256 blocks x 256.
// ---------------------------------------------------------------------------
__global__ void k_wo(const float* __restrict__ Wo, const float* __restrict__ bo)
{
    const int w    = blockIdx.x * 8 + (threadIdx.x >> 5);  // global warp id
    const int lane = threadIdx.x & 31;
    const int n = w >> 10;
    const int e = w & 1023;

    const float4* __restrict__ row = (const float4*)(Wo + (size_t)e * EMB);
    const float4* __restrict__ tv  = (const float4*)g_t[n];

    float acc = 0.f;
    #pragma unroll
    for (int i = lane; i < EMB / 4; i += 32) {
        float4 a = row[i];
        float4 b = tv[i];
        acc += a.x * b.x + a.y * b.y + a.z * b.z + a.w * b.w;
    }
    #pragma unroll
    for (int o = 16; o; o >>= 1) acc += __shfl_xor_sync(0xFFFFFFFFu, acc, o);

    if (lane == 0) g_y[n][e] = acc + bo[e];
}

// ---------------------------------------------------------------------------
// K4: broadcast y[n] to every sequence row.  Grid (64, NB) x 256, float4
// stores; each block writes 32 rows (128 KB), fully coalesced.
// ---------------------------------------------------------------------------
__global__ void k_broadcast(float* __restrict__ out)
{
    const int n = blockIdx.y;
    const int t = threadIdx.x;

    __shared__ float4 sy[EMB / 4];
    sy[t] = ((const float4*)g_y[n])[t];
    __syncthreads();

    float4* __restrict__ dst = (float4*)(out + (size_t)n * SLEN * EMB);
    const int s0 = blockIdx.x * 32;
    const float4 v = sy[t];
    #pragma unroll 8
    for (int s = s0; s < s0 + 32; ++s)
        dst[s * (EMB / 4) + t] = v;
}

// ---------------------------------------------------------------------------
// Inputs (metadata order): 0=values 1=keys 2=queries 3=mask 4=Wv 5=Wk 6=Wq
//                          7=Wo 8=bo.   Output: float32 [2, 2048, 1024].
// ---------------------------------------------------------------------------
extern "C" void kernel_launch(void* const* d_in, const int* in_sizes, int n_in,
                              void* d_out, int out_size)
{
    const float* values = (const float*)d_in[0];
    const float* Wv     = (const float*)d_in[4];
    const float* Wo     = (const float*)d_in[7];
    const float* bo     = (const float*)d_in[8];
    float*       out    = (float*)d_out;

    k_colsum_partial<<<dim3(SCH, NB), 256>>>(values);
    k_wv<<<NB, EMB>>>(Wv);
    k_wo<<<(NB * EMB) / 8, 256>>>(Wo, bo);
    k_broadcast<<<dim3(SLEN / 32, NB), 256>>>(out);
}